// round 9
// baseline (speedup 1.0000x reference)
#include <cuda_runtime.h>
#include <math.h>
#include <stdint.h>

#define BNR 32768
#define HOFF 458752
#define KOFF 2555904

// ------------- scratch globals -------------
__device__ __align__(16) float g_t1[BNR * 128];
__device__ __align__(16) float g_stats[1024];
__device__ __align__(16) float g_mean[BNR * 512];
__device__ __align__(16) float g_var[BNR * 512];
__device__ __align__(16) float g_aware[BNR * 512];
__device__ __align__(16) float g_U[BNR * 128];
__device__ __align__(16) float g_V[BNR * 128];

// ------------- tf32 mma helpers -------------
__device__ __forceinline__ float f2tf(float x) {
    uint32_t r;
    asm("cvt.rna.tf32.f32 %0, %1;" : "=r"(r) : "f"(x));
    return __uint_as_float(r);
}
__device__ __forceinline__ void mma_tf32(float* c, const uint32_t* a, const uint32_t* b) {
    asm volatile(
        "mma.sync.aligned.m16n8k8.row.col.f32.tf32.tf32.f32 "
        "{%0,%1,%2,%3}, {%4,%5,%6,%7}, {%8,%9}, {%0,%1,%2,%3};"
        : "+f"(c[0]), "+f"(c[1]), "+f"(c[2]), "+f"(c[3])
        : "r"(a[0]), "r"(a[1]), "r"(a[2]), "r"(a[3]), "r"(b[0]), "r"(b[1]));
}

// ------------- small kernels -------------
__global__ void zero_stats_k() { g_stats[threadIdx.x] = 0.f; }

__global__ void __launch_bounds__(128) ae_stats_k() {
    int c = threadIdx.x;
    size_t r0 = (size_t)blockIdx.x * 256;
    float s1 = 0.f, s2 = 0.f;
    for (int r = 0; r < 256; r++) {
        float v = g_t1[(r0 + r) * 128 + c];
        s1 += v; s2 += v * v;
    }
    atomicAdd(&g_stats[c], s1);
    atomicAdd(&g_stats[128 + c], s2);
}

__global__ void fin_ae_k() {
    int c = threadIdx.x;
    float m = g_stats[c] * (1.f / 32768.f);
    float v = g_stats[128 + c] * (1.f / 32768.f) - m * m;
    g_stats[256 + c] = m;
    g_stats[384 + c] = rsqrtf(v + 1e-5f);
}

__global__ void __launch_bounds__(256) aware_k(const float* __restrict__ noise) {
    int i = blockIdx.x * 256 + threadIdx.x;
    float4 m = ((const float4*)g_mean)[i];
    float4 v = ((const float4*)g_var)[i];
    float4 n = ((const float4*)noise)[i];
    float4 o;
    o.x = m.x + sqrtf(v.x) * n.x;
    o.y = m.y + sqrtf(v.y) * n.y;
    o.z = m.z + sqrtf(v.z) * n.z;
    o.w = m.w + sqrtf(v.w) * n.w;
    ((float4*)g_aware)[i] = o;
}

__global__ void __launch_bounds__(128) inf_stats_k() {
    int c = threadIdx.x;
    int b0 = blockIdx.x * 32;
    float A1 = 0.f, A2 = 0.f;
    for (int b = b0; b < b0 + 32; b++) {
        float su = 0.f, su2 = 0.f, sv = 0.f, sv2 = 0.f;
        #pragma unroll
        for (int i = 0; i < 8; i++) {
            float u = g_U[(size_t)(b * 8 + i) * 128 + c];
            float v = g_V[(size_t)(b * 8 + i) * 128 + c];
            su += u; su2 += u * u;
            sv += v; sv2 += v * v;
        }
        A1 += 8.f * (su + sv);
        A2 += 8.f * (su2 + sv2) + 2.f * su * sv;
    }
    atomicAdd(&g_stats[512 + c], A1);
    atomicAdd(&g_stats[640 + c], A2);
}

__global__ void fin_inf_k() {
    int c = threadIdx.x;
    const float im = 1.f / 262144.f;
    float m = g_stats[512 + c] * im;
    float v = g_stats[640 + c] * im - m * m;
    g_stats[768 + c] = m;
    g_stats[896 + c] = rsqrtf(v + 1e-5f);
}

// ------------- fused GRU megakernel: mlp1 + gates + GRU, 64 rows/block -----
// smem (floats): sIn 0(6400) sW1 6400(6912) [sGh aliases 0..12800]
//   sX1 13312(4352, stride 68) sH 17664(4352) sWg 22016(12800)
//   sGx 34816(12800) sB1 47616 sBih 47680 sBhh 47872   total 48064
__global__ void __launch_bounds__(256) gru_fused_k(
    const float* __restrict__ in_x, const float* __restrict__ w1,
    const float* __restrict__ b1, const float* __restrict__ wih,
    const float* __restrict__ bih, const float* __restrict__ whh,
    const float* __restrict__ bhh, const float* __restrict__ hin,
    float* __restrict__ hout) {
    extern __shared__ __align__(16) float sm[];
    float* sGh = sm;
    float* sIn = sm;
    float* sW1 = sm + 6400;
    float* sX1 = sm + 13312;
    float* sH  = sm + 17664;
    float* sWg = sm + 22016;
    float* sGx = sm + 34816;
    float* sB1 = sm + 47616;
    float* sBih = sm + 47680;
    float* sBhh = sm + 47872;
    int t = threadIdx.x, wid = t >> 5, lane = t & 31;
    int g = lane >> 2, tg = lane & 3;
    int m0 = blockIdx.x * 64;
    int mt = wid & 3, nh = wid >> 2;

    // phase 0 loads
    #pragma unroll
    for (int u = 0; u < 6; u++) {                 // in: 64x96
        int i = t + u * 256;
        int row = i / 24, c4 = (i % 24) * 4;
        float4 v = *(const float4*)(in_x + (size_t)(m0 + row) * 96 + c4);
        sIn[row * 100 + c4 + 0] = f2tf(v.x);
        sIn[row * 100 + c4 + 1] = f2tf(v.y);
        sIn[row * 100 + c4 + 2] = f2tf(v.z);
        sIn[row * 100 + c4 + 3] = f2tf(v.w);
    }
    #pragma unroll
    for (int u = 0; u < 6; u++) {                 // w1: 96x64
        int i = t + u * 256;
        int row = i >> 4, c4 = (i & 15) * 4;
        float4 v = *(const float4*)(w1 + row * 64 + c4);
        sW1[row * 72 + c4 + 0] = f2tf(v.x);
        sW1[row * 72 + c4 + 1] = f2tf(v.y);
        sW1[row * 72 + c4 + 2] = f2tf(v.z);
        sW1[row * 72 + c4 + 3] = f2tf(v.w);
    }
    #pragma unroll
    for (int u = 0; u < 4; u++) {                 // h: 64x64 fp32
        int i = t + u * 256;
        int row = i >> 4, c4 = (i & 15) * 4;
        *(float4*)&sH[row * 68 + c4] =
            *(const float4*)(hin + (size_t)(m0 + row) * 64 + c4);
    }
    if (t < 64) sB1[t] = b1[t];
    if (t < 192) sBih[t] = bih[t];
    __syncthreads();

    // phase 1: X1 = relu(in@w1 + b1)  M64 N64 K96
    {
        float a1[4][4];
        #pragma unroll
        for (int j = 0; j < 4; j++)
            #pragma unroll
            for (int q = 0; q < 4; q++) a1[j][q] = 0.f;
        #pragma unroll
        for (int k8 = 0; k8 < 12; k8++) {
            int kb = k8 * 8;
            uint32_t af[4];
            int base = (mt * 16 + g) * 100 + kb + tg;
            af[0] = __float_as_uint(sIn[base]);
            af[1] = __float_as_uint(sIn[base + 8 * 100]);
            af[2] = __float_as_uint(sIn[base + 4]);
            af[3] = __float_as_uint(sIn[base + 8 * 100 + 4]);
            #pragma unroll
            for (int j = 0; j < 4; j++) {
                int nb = nh * 32 + j * 8 + g;
                uint32_t bf[2];
                bf[0] = __float_as_uint(sW1[(kb + tg) * 72 + nb]);
                bf[1] = __float_as_uint(sW1[(kb + tg + 4) * 72 + nb]);
                mma_tf32(a1[j], af, bf);
            }
        }
        #pragma unroll
        for (int j = 0; j < 4; j++) {
            int col = nh * 32 + j * 8 + 2 * tg;
            int r = mt * 16 + g;
            float v00 = a1[j][0] + sB1[col], v01 = a1[j][1] + sB1[col + 1];
            float v10 = a1[j][2] + sB1[col], v11 = a1[j][3] + sB1[col + 1];
            sX1[r * 68 + col]     = f2tf(v00 > 0.f ? v00 : 0.f);
            sX1[r * 68 + col + 1] = f2tf(v01 > 0.f ? v01 : 0.f);
            sX1[(r + 8) * 68 + col]     = f2tf(v10 > 0.f ? v10 : 0.f);
            sX1[(r + 8) * 68 + col + 1] = f2tf(v11 > 0.f ? v11 : 0.f);
        }
    }
    __syncthreads();

    // phase 2: load w_ih, Gx = X1@w_ih + b_ih  (M64 N192 K64)
    #pragma unroll
    for (int u = 0; u < 12; u++) {
        int i = t + u * 256;
        int row = i / 48, c4 = (i % 48) * 4;
        float4 v = *(const float4*)(wih + row * 192 + c4);
        sWg[row * 200 + c4 + 0] = f2tf(v.x);
        sWg[row * 200 + c4 + 1] = f2tf(v.y);
        sWg[row * 200 + c4 + 2] = f2tf(v.z);
        sWg[row * 200 + c4 + 3] = f2tf(v.w);
    }
    __syncthreads();
    {
        float acc[12][4];
        #pragma unroll
        for (int j = 0; j < 12; j++)
            #pragma unroll
            for (int q = 0; q < 4; q++) acc[j][q] = 0.f;
        #pragma unroll
        for (int k8 = 0; k8 < 8; k8++) {
            int kb = k8 * 8;
            uint32_t af[4];
            int base = (mt * 16 + g) * 68 + kb + tg;
            af[0] = __float_as_uint(sX1[base]);
            af[1] = __float_as_uint(sX1[base + 8 * 68]);
            af[2] = __float_as_uint(sX1[base + 4]);
            af[3] = __float_as_uint(sX1[base + 8 * 68 + 4]);
            #pragma unroll
            for (int j = 0; j < 12; j++) {
                int nb = nh * 96 + j * 8 + g;
                uint32_t bf[2];
                bf[0] = __float_as_uint(sWg[(kb + tg) * 200 + nb]);
                bf[1] = __float_as_uint(sWg[(kb + tg + 4) * 200 + nb]);
                mma_tf32(acc[j], af, bf);
            }
        }
        #pragma unroll
        for (int j = 0; j < 12; j++) {
            int col = nh * 96 + j * 8 + 2 * tg;
            int r = mt * 16 + g;
            sGx[r * 200 + col]     = acc[j][0] + sBih[col];
            sGx[r * 200 + col + 1] = acc[j][1] + sBih[col + 1];
            sGx[(r + 8) * 200 + col]     = acc[j][2] + sBih[col];
            sGx[(r + 8) * 200 + col + 1] = acc[j][3] + sBih[col + 1];
        }
    }
    __syncthreads();

    // phase 3: load w_hh, Gh = h@w_hh + b_hh
    #pragma unroll
    for (int u = 0; u < 12; u++) {
        int i = t + u * 256;
        int row = i / 48, c4 = (i % 48) * 4;
        float4 v = *(const float4*)(whh + row * 192 + c4);
        sWg[row * 200 + c4 + 0] = f2tf(v.x);
        sWg[row * 200 + c4 + 1] = f2tf(v.y);
        sWg[row * 200 + c4 + 2] = f2tf(v.z);
        sWg[row * 200 + c4 + 3] = f2tf(v.w);
    }
    if (t < 192) sBhh[t] = bhh[t];
    __syncthreads();
    {
        float acc[12][4];
        #pragma unroll
        for (int j = 0; j < 12; j++)
            #pragma unroll
            for (int q = 0; q < 4; q++) acc[j][q] = 0.f;
        #pragma unroll
        for (int k8 = 0; k8 < 8; k8++) {
            int kb = k8 * 8;
            uint32_t af[4];
            int base = (mt * 16 + g) * 68 + kb + tg;
            af[0] = __float_as_uint(f2tf(sH[base]));
            af[1] = __float_as_uint(f2tf(sH[base + 8 * 68]));
            af[2] = __float_as_uint(f2tf(sH[base + 4]));
            af[3] = __float_as_uint(f2tf(sH[base + 8 * 68 + 4]));
            #pragma unroll
            for (int j = 0; j < 12; j++) {
                int nb = nh * 96 + j * 8 + g;
                uint32_t bf[2];
                bf[0] = __float_as_uint(sWg[(kb + tg) * 200 + nb]);
                bf[1] = __float_as_uint(sWg[(kb + tg + 4) * 200 + nb]);
                mma_tf32(acc[j], af, bf);
            }
        }
        #pragma unroll
        for (int j = 0; j < 12; j++) {
            int col = nh * 96 + j * 8 + 2 * tg;
            int r = mt * 16 + g;
            sGh[r * 200 + col]     = acc[j][0] + sBhh[col];
            sGh[r * 200 + col + 1] = acc[j][1] + sBhh[col + 1];
            sGh[(r + 8) * 200 + col]     = acc[j][2] + sBhh[col];
            sGh[(r + 8) * 200 + col + 1] = acc[j][3] + sBhh[col + 1];
        }
    }
    __syncthreads();

    // phase 4: GRU epilogue
    #pragma unroll
    for (int u = 0; u < 16; u++) {
        int e = t + u * 256;
        int row = e >> 6, j = e & 63;
        float xr = sGx[row * 200 + j], xz = sGx[row * 200 + j + 64],
              xn = sGx[row * 200 + j + 128];
        float hr = sGh[row * 200 + j], hz = sGh[row * 200 + j + 64],
              hn = sGh[row * 200 + j + 128];
        float rr = 1.f / (1.f + expf(-(xr + hr)));
        float zz = 1.f / (1.f + expf(-(xz + hz)));
        float nn = tanhf(xn + rr * hn);
        float h0 = sH[row * 68 + j];
        hout[(size_t)(m0 + row) * 64 + j] = (1.f - zz) * nn + zz * h0;
    }
}

// ------------- fused ae1 + U + V (tf32 mma), 64 rows/block, 2 passes -------
__global__ void __launch_bounds__(256) ae1uv_k(
    const float* __restrict__ h, const float* __restrict__ wae1,
    const float* __restrict__ bae1, const float* __restrict__ win1,
    const float* __restrict__ bin1) {
    extern __shared__ __align__(16) float sm[];
    float* sH = sm;            // 64x68 fp32
    float* sW = sm + 4352;     // 64x200 tf32
    float* sB = sm + 17152;    // 384
    int t = threadIdx.x, wid = t >> 5, lane = t & 31;
    int g = lane >> 2, tg = lane & 3;
    int m0 = blockIdx.x * 64;
    int mt = wid & 3, nh = wid >> 2;

    #pragma unroll
    for (int u = 0; u < 4; u++) {
        int i = t + u * 256;
        int row = i >> 4, c4 = (i & 15) * 4;
        *(float4*)&sH[row * 68 + c4] =
            *(const float4*)(h + (size_t)(m0 + row) * 64 + c4);
    }
    for (int i = t; i < 384; i += 256)
        sB[i] = (i < 128) ? bae1[i] : (i < 256 ? 0.f : bin1[i - 256]);
    __syncthreads();

    for (int p = 0; p < 2; p++) {
        for (int i = t; i < 12288; i += 256) {
            int k = i / 192, c = i % 192;
            int gc = p * 192 + c;
            float w;
            if (gc < 128) w = wae1[k * 128 + gc];
            else if (gc < 256) w = win1[k * 128 + gc - 128];
            else w = win1[(64 + k) * 128 + gc - 256];
            sW[k * 200 + c] = f2tf(w);
        }
        __syncthreads();
        float acc[12][4];
        #pragma unroll
        for (int j = 0; j < 12; j++)
            #pragma unroll
            for (int q = 0; q < 4; q++) acc[j][q] = 0.f;
        #pragma unroll
        for (int k8 = 0; k8 < 8; k8++) {
            int kb = k8 * 8;
            uint32_t af[4];
            int base = (mt * 16 + g) * 68 + kb + tg;
            af[0] = __float_as_uint(f2tf(sH[base]));
            af[1] = __float_as_uint(f2tf(sH[base + 8 * 68]));
            af[2] = __float_as_uint(f2tf(sH[base + 4]));
            af[3] = __float_as_uint(f2tf(sH[base + 8 * 68 + 4]));
            #pragma unroll
            for (int j = 0; j < 12; j++) {
                int nb = nh * 96 + j * 8 + g;
                uint32_t bf[2];
                bf[0] = __float_as_uint(sW[(kb + tg) * 200 + nb]);
                bf[1] = __float_as_uint(sW[(kb + tg + 4) * 200 + nb]);
                mma_tf32(acc[j], af, bf);
            }
        }
        #pragma unroll
        for (int j = 0; j < 12; j++) {
            int cl = nh * 96 + j * 8 + 2 * tg;
            int gc = p * 192 + cl;
            int r = m0 + mt * 16 + g;
            float v0 = acc[j][0] + sB[gc], v1 = acc[j][1] + sB[gc + 1];
            float v2 = acc[j][2] + sB[gc], v3 = acc[j][3] + sB[gc + 1];
            float* dst;
            int c;
            if (gc < 128)      { dst = g_t1; c = gc; }
            else if (gc < 256) { dst = g_U;  c = gc - 128; }
            else               { dst = g_V;  c = gc - 256; }
            dst[(size_t)r * 128 + c] = v0;
            dst[(size_t)r * 128 + c + 1] = v1;
            dst[(size_t)(r + 8) * 128 + c] = v2;
            dst[(size_t)(r + 8) * 128 + c + 1] = v3;
        }
        __syncthreads();
    }
}

// ------------- ae2: tf32 mma GEMM, BN+lrelu fused into A load ---------------
__global__ void __launch_bounds__(256) ae2_k(
    const float* __restrict__ Araw, const float* __restrict__ Bw,
    const float* __restrict__ bias,
    const float* __restrict__ gg, const float* __restrict__ bb) {
    __shared__ __align__(16) float As[128 * 36];
    __shared__ __align__(16) float Bs[32 * 136];
    __shared__ float sScale[128], sShift[128];
    int t = threadIdx.x, wid = t >> 5, lane = t & 31;
    int g = lane >> 2, tg = lane & 3;
    int m0 = blockIdx.y * 128, n0 = blockIdx.x * 128;
    int m0w = (wid & 3) * 32, n0w = (wid >> 2) * 64;

    if (t < 128) {
        float sc = g_stats[384 + t] * gg[t];
        sScale[t] = sc;
        sShift[t] = bb[t] - g_stats[256 + t] * sc;
    }
    __syncthreads();

    float acc[2][8][4];
    #pragma unroll
    for (int i = 0; i < 2; i++)
        #pragma unroll
        for (int j = 0; j < 8; j++)
            #pragma unroll
            for (int q = 0; q < 4; q++) acc[i][j][q] = 0.f;

    for (int k0 = 0; k0 < 128; k0 += 32) {
        #pragma unroll
        for (int u = 0; u < 4; u++) {
            int idx = t + u * 256;
            int row = idx >> 3, c4 = (idx & 7) * 4;
            float4 v = *(const float4*)(Araw + (size_t)(m0 + row) * 128 + k0 + c4);
            float vv[4] = {v.x, v.y, v.z, v.w};
            #pragma unroll
            for (int jj = 0; jj < 4; jj++) {
                int col = k0 + c4 + jj;
                float x = vv[jj] * sScale[col] + sShift[col];
                x = x >= 0.f ? x : 0.01f * x;
                As[row * 36 + c4 + jj] = f2tf(x);
            }
        }
        #pragma unroll
        for (int u = 0; u < 4; u++) {
            int idx = t + u * 256;
            int kr = idx >> 5, n4 = (idx & 31) * 4;
            float4 v = *(const float4*)(Bw + (size_t)(k0 + kr) * 1024 + n0 + n4);
            Bs[kr * 136 + n4 + 0] = f2tf(v.x);
            Bs[kr * 136 + n4 + 1] = f2tf(v.y);
            Bs[kr * 136 + n4 + 2] = f2tf(v.z);
            Bs[kr * 136 + n4 + 3] = f2tf(v.w);
        }
        __syncthreads();
        #pragma unroll
        for (int k8 = 0; k8 < 4; k8++) {
            int kb = k8 * 8;
            uint32_t af[2][4];
            #pragma unroll
            for (int i = 0; i < 2; i++) {
                int base = (m0w + i * 16 + g) * 36 + kb + tg;
                af[i][0] = __float_as_uint(As[base]);
                af[i][1] = __float_as_uint(As[base + 8 * 36]);
                af[i][2] = __float_as_uint(As[base + 4]);
                af[i][3] = __float_as_uint(As[base + 8 * 36 + 4]);
            }
            #pragma unroll
            for (int j = 0; j < 8; j++) {
                uint32_t bf[2];
                int nb = n0w + j * 8 + g;
                bf[0] = __float_as_uint(Bs[(kb + tg) * 136 + nb]);
                bf[1] = __float_as_uint(Bs[(kb + tg + 4) * 136 + nb]);
                mma_tf32(acc[0][j], af[0], bf);
                mma_tf32(acc[1][j], af[1], bf);
            }
        }
        __syncthreads();
    }
    bool isvar = (n0 >= 512);
    #pragma unroll
    for (int i = 0; i < 2; i++) {
        #pragma unroll
        for (int j = 0; j < 8; j++) {
            int col = n0 + n0w + j * 8 + 2 * tg;
            float b0 = bias[col], b1 = bias[col + 1];
            int r0 = m0 + m0w + i * 16 + g;
            float v00 = acc[i][j][0] + b0, v01 = acc[i][j][1] + b1;
            float v10 = acc[i][j][2] + b0, v11 = acc[i][j][3] + b1;
            if (isvar) {
                int c = col - 512;
                *(float2*)&g_var[(size_t)r0 * 512 + c] =
                    make_float2(fmaxf(expf(v00), 0.002f), fmaxf(expf(v01), 0.002f));
                *(float2*)&g_var[(size_t)(r0 + 8) * 512 + c] =
                    make_float2(fmaxf(expf(v10), 0.002f), fmaxf(expf(v11), 0.002f));
            } else {
                *(float2*)&g_mean[(size_t)r0 * 512 + col] = make_float2(v00, v01);
                *(float2*)&g_mean[(size_t)(r0 + 8) * 512 + col] = make_float2(v10, v11);
            }
        }
    }
}

// ------------- infer stage-2 (tf32 mma) fused with KLD ---------------------
__global__ void __launch_bounds__(256) inf2_k(
    const float* __restrict__ w2, const float* __restrict__ b2,
    const float* __restrict__ gi, const float* __restrict__ bei,
    float* __restrict__ kout) {
    extern __shared__ __align__(16) float sm[];
    float* sW  = sm;
    float* sA2 = sW + 128 * 136;
    float* sU  = sA2 + 64 * 132;
    float* sV  = sU + 1024;
    float* sred = sV + 1024;
    int t = threadIdx.x, b = blockIdx.x;
    int wid = t >> 5, lane = t & 31;
    int g = lane >> 2, tg = lane & 3;

    for (int i = t; i < 1024; i += 256) {
        sU[i] = g_U[(size_t)b * 1024 + i];
        sV[i] = g_V[(size_t)b * 1024 + i];
    }
    #pragma unroll
    for (int u = 0; u < 16; u++) {
        int idx = t + u * 256;
        int row = idx >> 5, c4 = (idx & 31) * 4;
        float4 v = *(const float4*)(w2 + row * 128 + c4);
        sW[row * 136 + c4 + 0] = f2tf(v.x);
        sW[row * 136 + c4 + 1] = f2tf(v.y);
        sW[row * 136 + c4 + 2] = f2tf(v.z);
        sW[row * 136 + c4 + 3] = f2tf(v.w);
    }
    __syncthreads();
    for (int e = t; e < 8192; e += 256) {
        int row = e >> 7, c = e & 127;
        int i = row >> 3, j = row & 7;
        float v = (sU[i * 128 + c] + sV[j * 128 + c] - g_stats[768 + c]) *
                  g_stats[896 + c] * gi[c] + bei[c];
        v = v >= 0.f ? v : 0.01f * v;
        sA2[row * 132 + c] = f2tf(v);
    }
    __syncthreads();

    int mt = wid & 3, n0w = (wid >> 2) * 64;
    float acc[8][4];
    #pragma unroll
    for (int j = 0; j < 8; j++)
        #pragma unroll
        for (int q = 0; q < 4; q++) acc[j][q] = 0.f;
    #pragma unroll
    for (int k8 = 0; k8 < 16; k8++) {
        int kb = k8 * 8;
        uint32_t af[4];
        int base = (mt * 16 + g) * 132 + kb + tg;
        af[0] = __float_as_uint(sA2[base]);
        af[1] = __float_as_uint(sA2[base + 8 * 132]);
        af[2] = __float_as_uint(sA2[base + 4]);
        af[3] = __float_as_uint(sA2[base + 8 * 132 + 4]);
        #pragma unroll
        for (int j = 0; j < 8; j++) {
            uint32_t bf[2];
            int nb = n0w + j * 8 + g;
            bf[0] = __float_as_uint(sW[(kb + tg) * 136 + nb]);
            bf[1] = __float_as_uint(sW[(kb + tg + 4) * 136 + nb]);
            mma_tf32(acc[j], af, bf);
        }
    }
    __syncthreads();
    #pragma unroll
    for (int j = 0; j < 8; j++) {
        int col = n0w + j * 8 + 2 * tg;
        int r0 = mt * 16 + g;
        sA2[r0 * 132 + col] = acc[j][0] + b2[col];
        sA2[r0 * 132 + col + 1] = acc[j][1] + b2[col + 1];
        sA2[(r0 + 8) * 132 + col] = acc[j][2] + b2[col];
        sA2[(r0 + 8) * 132 + col + 1] = acc[j][3] + b2[col + 1];
    }
    __syncthreads();

    float s = 0.f;
    for (int e = t; e < 4096; e += 256) {
        int row = e >> 6, d = e & 63;
        float im = sA2[row * 132 + d];
        float iv = fmaxf(expf(sA2[row * 132 + 64 + d]), 0.002f);
        int i = row >> 3, j = row & 7;
        size_t gr = (size_t)(b * 8 + i) * 512 + j * 64 + d;
        float m = g_mean[gr], v = g_var[gr];
        float dd = m - im;
        s += 0.5f * (logf(iv) - logf(v)) + 0.5f * (v + dd * dd) / iv - 0.5f;
    }
    for (int off = 16; off; off >>= 1) s += __shfl_xor_sync(~0u, s, off);
    if ((t & 31) == 0) sred[t >> 5] = s;
    __syncthreads();
    if (t < 8) {
        s = sred[t];
        #pragma unroll
        for (int off = 4; off; off >>= 1) s += __shfl_xor_sync(0xffu, s, off);
        if (t == 0) kout[b] = s * (1.f / 4096.f);
    }
}

// ------------- attention + mlp2 fused: 8 rows/block ------------------------
// smem floats: sA 0(4352) sW 4352(8704) sQ 13056(8448) sK 21504(8448)
//   sV 29952(8448) sgln 38400 sbln 38464 sW2 38528(9216) sH2 47744(512)
//   sB2 48256(16) sPart 48272(224)  total 48496
__global__ void __launch_bounds__(256) attn2_k(
    const float* __restrict__ wq, const float* __restrict__ wk,
    const float* __restrict__ wv, const float* __restrict__ wfc,
    const float* __restrict__ gln, const float* __restrict__ bln,
    const float* __restrict__ hsrc, const float* __restrict__ w2,
    const float* __restrict__ b2, float* __restrict__ qout) {
    extern __shared__ __align__(16) float sm[];
    float* sA = sm;
    float* sW = sm + 4352;
    float* sQ = sm + 13056;
    float* sK = sm + 21504;
    float* sV = sm + 29952;
    float* sgln = sm + 38400;
    float* sbln = sm + 38464;
    float* sW2 = sm + 38528;
    float* sH2 = sm + 47744;
    float* sB2 = sm + 48256;
    float* sPart = sm + 48272;
    float* sAtt = sQ;                 // reuse after fc
    int t = threadIdx.x, wid = t >> 5, lane = t & 31;
    int g = lane >> 2, tg = lane & 3;
    int mw = (wid & 3) * 16;
    int nw2 = wid >> 2;
    size_t rbase = (size_t)blockIdx.x * 8;

    #pragma unroll
    for (int u = 0; u < 4; u++) {
        int i = t + u * 256;
        int tok = i >> 4, c4 = (i & 15) * 4;
        float4 v = *(const float4*)(g_aware + rbase * 512 + tok * 64 + c4);
        *(float4*)&sA[tok * 68 + c4] = v;
    }
    if (t < 64) sgln[t] = gln[t];
    else if (t < 128) sbln[t - 64] = bln[t - 64];
    for (int i = t; i < 8064; i += 256) {            // w_mlp2 576x14 -> stride 16
        int row = i / 14, c = i % 14;
        sW2[row * 16 + c] = w2[i];
    }
    for (int i = t; i < 512; i += 256)
        sH2[i] = hsrc[rbase * 64 + i];
    if (t < 14) sB2[t] = b2[t];

    // ---- QKV ----
    const float* Wsrc[3] = {wq, wk, wv};
    float* Dst[3] = {sQ, sK, sV};
    for (int w = 0; w < 3; w++) {
        #pragma unroll
        for (int u = 0; u < 8; u++) {
            int i = t + u * 256;
            int row = i >> 5, c4 = (i & 31) * 4;
            float4 v = *(const float4*)(Wsrc[w] + row * 128 + c4);
            sW[row * 132 + c4 + 0] = f2tf(v.x);
            sW[row * 132 + c4 + 1] = f2tf(v.y);
            sW[row * 132 + c4 + 2] = f2tf(v.z);
            sW[row * 132 + c4 + 3] = f2tf(v.w);
        }
        __syncthreads();
        float acc[8][4];
        #pragma unroll
        for (int j = 0; j < 8; j++)
            #pragma unroll
            for (int q = 0; q < 4; q++) acc[j][q] = 0.f;
        #pragma unroll
        for (int k8 = 0; k8 < 8; k8++) {
            int kb = k8 * 8;
            uint32_t af[4];
            int base = (mw + g) * 68 + kb + tg;
            af[0] = __float_as_uint(f2tf(sA[base]));
            af[1] = __float_as_uint(f2tf(sA[base + 8 * 68]));
            af[2] = __float_as_uint(f2tf(sA[base + 4]));
            af[3] = __float_as_uint(f2tf(sA[base + 8 * 68 + 4]));
            #pragma unroll
            for (int j = 0; j < 8; j++) {
                int nb = nw2 * 64 + j * 8 + g;
                uint32_t bf[2];
                bf[0] = __float_as_uint(sW[(kb + tg) * 132 + nb]);
                bf[1] = __float_as_uint(sW[(kb + tg + 4) * 132 + nb]);
                mma_tf32(acc[j], af, bf);
            }
        }
        float* D = Dst[w];
        #pragma unroll
        for (int j = 0; j < 8; j++) {
            int col = nw2 * 64 + j * 8 + 2 * tg;
            int cm = (col >> 5) * 33 + (col & 31);
            D[(mw + g) * 132 + cm] = acc[j][0];
            D[(mw + g) * 132 + cm + 1] = acc[j][1];
            D[(mw + g + 8) * 132 + cm] = acc[j][2];
            D[(mw + g + 8) * 132 + cm + 1] = acc[j][3];
        }
        __syncthreads();
    }

    // ---- scores + softmax ----
    int srow = wid;
    int h = (t >> 3) & 3, q = t & 7;
    int tokq = srow * 8 + q;
    float qd[32];
    #pragma unroll
    for (int d = 0; d < 32; d++) qd[d] = sQ[tokq * 132 + h * 33 + d];
    float p[8];
    #pragma unroll
    for (int k = 0; k < 8; k++) {
        int tokk = srow * 8 + k;
        float s = 0.f;
        #pragma unroll
        for (int d = 0; d < 32; d++) s += qd[d] * sK[tokk * 132 + h * 33 + d];
        p[k] = s * 0.17677669529663687f;
    }
    float mx = p[0];
    #pragma unroll
    for (int k = 1; k < 8; k++) mx = fmaxf(mx, p[k]);
    float ssum = 0.f;
    #pragma unroll
    for (int k = 0; k < 8; k++) { p[k] = __expf(p[k] - mx); ssum += p[k]; }
    float inv = 1.f / ssum;
    #pragma unroll
    for (int k = 0; k < 8; k++) p[k] *= inv;
    __syncthreads();

    // ---- AV -> O (overwrites sQ) ----
    #pragma unroll
    for (int d = 0; d < 32; d++) {
        float o = 0.f;
        #pragma unroll
        for (int k = 0; k < 8; k++)
            o += p[k] * sV[(srow * 8 + k) * 132 + h * 33 + d];
        sQ[tokq * 132 + h * 33 + d] = f2tf(o);
    }

    // ---- wfc load ----
    #pragma unroll
    for (int u = 0; u < 8; u++) {
        int i = t + u * 256;
        int row = i >> 4, c4 = (i & 15) * 4;
        float4 v = *(const float4*)(wfc + row * 64 + c4);
        sW[row * 68 + c4 + 0] = f2tf(v.x);
        sW[row * 68 + c4 + 1] = f2tf(v.y);
        sW[row * 68 + c4 + 2] = f2tf(v.z);
        sW[row * 68 + c4 + 3] = f2tf(v.w);
    }
    __syncthreads();

    // ---- fc ----
    int nwf = (wid >> 2) * 32;
    float acc2[4][4];
    #pragma unroll
    for (int j = 0; j < 4; j++)
        #pragma unroll
        for (int q2 = 0; q2 < 4; q2++) acc2[j][q2] = 0.f;
    #pragma unroll
    for (int k8 = 0; k8 < 16; k8++) {
        int kb = k8 * 8;
        int cmk = (kb >> 5) * 33 + (kb & 31);
        uint32_t af[4];
        int b0 = (mw + g) * 132 + cmk + tg;
        af[0] = __float_as_uint(sQ[b0]);
        af[1] = __float_as_uint(sQ[b0 + 8 * 132]);
        af[2] = __float_as_uint(sQ[b0 + 4]);
        af[3] = __float_as_uint(sQ[b0 + 8 * 132 + 4]);
        #pragma unroll
        for (int j = 0; j < 4; j++) {
            int nb = nwf + j * 8 + g;
            uint32_t bf[2];
            bf[0] = __float_as_uint(sW[(kb + tg) * 68 + nb]);
            bf[1] = __float_as_uint(sW[(kb + tg + 4) * 68 + nb]);
            mma_tf32(acc2[j], af, bf);
        }
    }
    __syncthreads();
    #pragma unroll
    for (int j = 0; j < 4; j++) {
        int col = nwf + j * 8 + 2 * tg;
        int tok = mw + g;
        sK[tok * 132 + col]     = acc2[j][0] + sA[tok * 68 + col];
        sK[tok * 132 + col + 1] = acc2[j][1] + sA[tok * 68 + col + 1];
        sK[(tok + 8) * 132 + col]     = acc2[j][2] + sA[(tok + 8) * 68 + col];
        sK[(tok + 8) * 132 + col + 1] = acc2[j][3] + sA[(tok + 8) * 68 + col + 1];
    }
    __syncthreads();

    // ---- LayerNorm -> sAtt ----
    int tok = t >> 2, part = t & 3;
    float vals[16];
    float s1 = 0.f, s2 = 0.f;
    #pragma unroll
    for (int i = 0; i < 16; i++) {
        float v = sK[tok * 132 + part * 16 + i];
        vals[i] = v; s1 += v; s2 += v * v;
    }
    s1 += __shfl_xor_sync(~0u, s1, 1); s2 += __shfl_xor_sync(~0u, s2, 1);
    s1 += __shfl_xor_sync(~0u, s1, 2); s2 += __shfl_xor_sync(~0u, s2, 2);
    float mu = s1 * (1.f / 64.f);
    float var = s2 * (1.f / 64.f) - mu * mu;
    float is = rsqrtf(var + 1e-6f);
    {
        int arow = tok >> 3, agent = tok & 7;
        float* ap = sAtt + arow * 512 + agent * 64 + part * 16;
        #pragma unroll
        for (int i = 0; i < 16; i++)
            ap[i] = (vals[i] - mu) * is * sgln[part * 16 + i] + sbln[part * 16 + i];
    }
    __syncthreads();

    // ---- mlp2: q = [h | att] @ w_mlp2 + b ----
    if (t < 224) {
        int row = t / 28, rem = t % 28, kh = rem / 14, col = rem % 14;
        float acc = 0.f;
        if (kh == 0) {
            acc = sB2[col];
            #pragma unroll 8
            for (int k = 0; k < 64; k++)
                acc += sH2[row * 64 + k] * sW2[k * 16 + col];
            #pragma unroll 8
            for (int k = 64; k < 288; k++)
                acc += sAtt[row * 512 + k - 64] * sW2[k * 16 + col];
        } else {
            #pragma unroll 8
            for (int k = 288; k < 576; k++)
                acc += sAtt[row * 512 + k - 64] * sW2[k * 16 + col];
        }
        sPart[t] = acc;
    }
    __syncthreads();
    if (t < 112) {
        int row = t / 14, col = t % 14;
        qout[(rbase + row) * 14 + col] = sPart[row * 28 + col] + sPart[row * 28 + 14 + col];
    }
}

// ------------- launcher -------------
extern "C" void kernel_launch(void* const* d_in, const int* in_sizes, int n_in,
                              void* d_out, int out_size) {
    const float* in_x   = (const float*)d_in[0];
    const float* hid    = (const float*)d_in[1];
    const float* noise  = (const float*)d_in[2];
    const float* w_mlp1 = (const float*)d_in[3];
    const float* b_mlp1 = (const float*)d_in[4];
    const float* w_ih   = (const float*)d_in[5];
    const float* b_ih   = (const float*)d_in[6];
    const float* w_hh   = (const float*)d_in[7];
    const float* b_hh   = (const float*)d_in[8];
    const float* w_ae1  = (const float*)d_in[9];
    const float* b_ae1  = (const float*)d_in[10];
    const float* g_ae   = (const float*)d_in[11];
    const float* be_ae  = (const float*)d_in[12];
    const float* w_ae2  = (const float*)d_in[13];
    const float* b_ae2  = (const float*)d_in[14];
    const float* w_in1  = (const float*)d_in[15];
    const float* b_in1  = (const float*)d_in[16];
    const float* g_in   = (const float*)d_in[17];
    const float* be_in  = (const float*)d_in[18];
    const float* w_in2  = (const float*)d_in[19];
    const float* b_in2  = (const float*)d_in[20];
    const float* w_q    = (const float*)d_in[21];
    const float* w_k    = (const float*)d_in[22];
    const float* w_v    = (const float*)d_in[23];
    const float* w_fc   = (const float*)d_in[24];
    const float* gln    = (const float*)d_in[25];
    const float* bln    = (const float*)d_in[26];
    const float* w_mlp2 = (const float*)d_in[27];
    const float* b_mlp2 = (const float*)d_in[28];

    float* out  = (float*)d_out;
    float* qout = out;
    float* hout = out + HOFF;
    float* kout = out + KOFF;

    void* pt1;
    cudaGetSymbolAddress(&pt1, g_t1);

    size_t gru_smem  = (size_t)48064 * 4;
    size_t aeuv_smem = (size_t)17536 * 4;
    size_t inf2_smem = (size_t)(128 * 136 + 64 * 132 + 1024 + 1024 + 8) * 4;
    size_t attn_smem = (size_t)48496 * 4;
    cudaFuncSetAttribute(gru_fused_k, cudaFuncAttributeMaxDynamicSharedMemorySize, (int)gru_smem);
    cudaFuncSetAttribute(ae1uv_k, cudaFuncAttributeMaxDynamicSharedMemorySize, (int)aeuv_smem);
    cudaFuncSetAttribute(inf2_k, cudaFuncAttributeMaxDynamicSharedMemorySize, (int)inf2_smem);
    cudaFuncSetAttribute(attn2_k, cudaFuncAttributeMaxDynamicSharedMemorySize, (int)attn_smem);

    gru_fused_k<<<512, 256, gru_smem>>>(in_x, w_mlp1, b_mlp1, w_ih, b_ih,
                                        w_hh, b_hh, hid, hout);
    ae1uv_k<<<512, 256, aeuv_smem>>>(hout, w_ae1, b_ae1, w_in1, b_in1);
    zero_stats_k<<<1, 1024>>>();
    ae_stats_k<<<128, 128>>>();
    fin_ae_k<<<1, 128>>>();
    ae2_k<<<dim3(8, 256), 256>>>((const float*)pt1, w_ae2, b_ae2, g_ae, be_ae);
    aware_k<<<16384, 256>>>(noise);
    inf_stats_k<<<128, 128>>>();
    fin_inf_k<<<1, 128>>>();
    inf2_k<<<4096, 256, inf2_smem>>>(w_in2, b_in2, g_in, be_in, kout);
    attn2_k<<<4096, 256, attn_smem>>>(w_q, w_k, w_v, w_fc, gln, bln,
                                      hout, w_mlp2, b_mlp2, qout);
}